// round 5
// baseline (speedup 1.0000x reference)
#include <cuda_runtime.h>
#include <cstdint>
#include <cstddef>

// ---------------------------------------------------------------------------
// ConvPool (BPNet-style): 1x1 proj GEMM -> 7x dilated conv tower (residual,
// relu) -> profile conv (K=75) + atpm head (mean -> linear -> softplus).
// R5: double-buffered smem (2 stages, dynamic 83KB), ONE __syncthreads per
// 32-deep K-chunk; FFMA2 micro-kernel unchanged.
// ---------------------------------------------------------------------------

#define NPEAK 128          // B * NUM_PEAKS
#define HIDC  256
#define MOTIF_C 640
#define TS    1000         // per-row t stride
#define BUF_ELEMS (NPEAK * HIDC * TS + 4096)

// stage layout in dynamic smem: As (32x68) then Bs (32x256), per stage
#define AS_FLOATS (32 * 68)
#define STAGE_FLOATS (AS_FLOATS + 32 * 256)   // 10368 floats = 41472 B
#define SMEM_BYTES (2 * STAGE_FLOATS * 4)     // 82944 B

typedef unsigned long long ull_t;

__device__ float g_bufA[BUF_ELEMS];
__device__ float g_bufB[BUF_ELEMS];

__device__ __forceinline__ float softplusf(float x) {
    return fmaxf(x, 0.0f) + log1pf(expf(-fabsf(x)));
}

__device__ __forceinline__ ull_t pack2(float x, float y) {
    ull_t r;
    asm("mov.b64 %0, {%1, %2};" : "=l"(r) : "f"(x), "f"(y));
    return r;
}
__device__ __forceinline__ float2 unpack2(ull_t v) {
    float2 r;
    asm("mov.b64 {%0, %1}, %2;" : "=f"(r.x), "=f"(r.y) : "l"(v));
    return r;
}
__device__ __forceinline__ void ffma2(ull_t& d, ull_t a, ull_t b) {
    asm("fma.rn.f32x2 %0, %1, %2, %0;" : "+l"(d) : "l"(a), "l"(b));
}

// 8x8 micro-kernel (8 ch x 4 f32x2 pairs) over a 32-deep K tile.
// As: [k][c] stride 68; Bs: [k][t] stride 256.
__device__ __forceinline__ void compute32(
    const float* __restrict__ As, const float* __restrict__ Bs,
    int tx, int ty, ull_t acc[8][4])
{
#pragma unroll
    for (int kk = 0; kk < 32; kk++) {
        float4 a0 = *(const float4*)(As + kk * 68 + ty * 4);
        float4 a1 = *(const float4*)(As + kk * 68 + 32 + ty * 4);
        ull_t av[8];
        av[0] = pack2(a0.x, a0.x); av[1] = pack2(a0.y, a0.y);
        av[2] = pack2(a0.z, a0.z); av[3] = pack2(a0.w, a0.w);
        av[4] = pack2(a1.x, a1.x); av[5] = pack2(a1.y, a1.y);
        av[6] = pack2(a1.z, a1.z); av[7] = pack2(a1.w, a1.w);
        ulonglong2 b0 = *(const ulonglong2*)(Bs + kk * 256 + tx * 4);
        ulonglong2 b1 = *(const ulonglong2*)(Bs + kk * 256 + 128 + tx * 4);
        ull_t bv[4] = {b0.x, b0.y, b1.x, b1.y};
#pragma unroll
        for (int i = 0; i < 8; i++)
#pragma unroll
            for (int j = 0; j < 4; j++)
                ffma2(acc[i][j], av[i], bv[j]);
    }
}

// ---------------------------------------------------------------------------
// Projection GEMM: out[p][c][t] = sum_m x[pos][m] * W[c][m] + b[c]
// ---------------------------------------------------------------------------
__device__ __forceinline__ void pj_loadA(const float* __restrict__ w, int c0,
                                         int tid, int k0, float pA[8])
{
#pragma unroll
    for (int i = 0; i < 8; i++) {
        int idx = tid + i * 256;
        int kk = idx & 31, cc = idx >> 5;
        pA[i] = w[(size_t)(c0 + cc) * MOTIF_C + k0 + kk];
    }
}
__device__ __forceinline__ void pj_loadB(const float* __restrict__ x, int pos0,
                                         int tid, int k0, float4 pB[8])
{
#pragma unroll
    for (int i = 0; i < 8; i++) {
        int idx = tid + i * 256;
        int f4 = idx & 7, pl = idx >> 3;
        pB[i] = *(const float4*)(x + (size_t)(pos0 + pl) * MOTIF_C + k0 + f4 * 4);
    }
}

__global__ __launch_bounds__(256) void proj_kernel(
    const float* __restrict__ x, const float* __restrict__ w,
    const float* __restrict__ bias, float* __restrict__ out)
{
    extern __shared__ float sm[];
    const int tid = threadIdx.x;
    const int tx = tid & 31, ty = tid >> 5;
    const int pos0 = blockIdx.x * 256;
    const int c0 = blockIdx.y * 64;

    ull_t acc[8][4];
#pragma unroll
    for (int i = 0; i < 8; i++)
#pragma unroll
        for (int j = 0; j < 4; j++) acc[i][j] = 0ull;

    float pA[8];
    float4 pB[8];
    pj_loadA(w, c0, tid, 0, pA);
    pj_loadB(x, pos0, tid, 0, pB);

#pragma unroll 1
    for (int ch = 0; ch < MOTIF_C / 32; ch++) {
        float* Asw = sm + (ch & 1) * STAGE_FLOATS;
        float* Bsw = Asw + AS_FLOATS;
        // store staged regs (chunk ch) into stage ch&1
#pragma unroll
        for (int i = 0; i < 8; i++) {
            int idx = tid + i * 256;
            Asw[(idx & 31) * 68 + (idx >> 5)] = pA[i];
        }
#pragma unroll
        for (int i = 0; i < 8; i++) {
            int idx = tid + i * 256;
            int f4 = idx & 7, pl = idx >> 3;
            Bsw[(f4 * 4 + 0) * 256 + pl] = pB[i].x;
            Bsw[(f4 * 4 + 1) * 256 + pl] = pB[i].y;
            Bsw[(f4 * 4 + 2) * 256 + pl] = pB[i].z;
            Bsw[(f4 * 4 + 3) * 256 + pl] = pB[i].w;
        }
        __syncthreads();
        if (ch + 1 < MOTIF_C / 32) {
            pj_loadA(w, c0, tid, (ch + 1) * 32, pA);
            pj_loadB(x, pos0, tid, (ch + 1) * 32, pB);
        }
        compute32(Asw, Bsw, tx, ty, acc);
    }

#pragma unroll
    for (int ii = 0; ii < 8; ii++) {
        int c = c0 + ((ii < 4) ? (ty * 4 + ii) : (32 + ty * 4 + ii - 4));
        float bvv = bias[c];
#pragma unroll
        for (int g = 0; g < 2; g++) {
            float2 u0 = unpack2(acc[ii][g * 2 + 0]);
            float2 u1 = unpack2(acc[ii][g * 2 + 1]);
            float v[4] = {u0.x, u0.y, u1.x, u1.y};
#pragma unroll
            for (int e = 0; e < 4; e++) {
                int pos = pos0 + g * 128 + tx * 4 + e;
                int pb = pos / 1000;
                int tb = pos - pb * 1000;
                out[(size_t)pb * (HIDC * TS) + (size_t)c * TS + tb] = v[e] + bvv;
            }
        }
    }
}

// ---------------------------------------------------------------------------
// Dilated conv: hout[p][c][t] = relu(sum_{ci,k} W[c][ci][k]*hin[p][ci][t+k*dil]+b[c])
//                               + hin[p][c][t+dil]
// 24 chunks = 3 taps x 8 ci-blocks; 2-stage single-sync pipeline.
// ---------------------------------------------------------------------------
__device__ __forceinline__ void dc_loadA(const float* __restrict__ w, int c0,
                                         int tid, int chunk, float pA[8])
{
    int k = chunk >> 3, ci0 = (chunk & 7) << 5;
#pragma unroll
    for (int i = 0; i < 8; i++) {
        int idx = tid + i * 256;
        int ci = idx & 31, cc = idx >> 5;
        pA[i] = w[(size_t)(c0 + cc) * 768 + (ci0 + ci) * 3 + k];
    }
}
__device__ __forceinline__ void dc_loadB(const float* __restrict__ hp, int t0,
                                         int dil, int tid, int chunk,
                                         float2 pB[8][2])
{
    int k = chunk >> 3, ci0 = (chunk & 7) << 5;
    int toff = t0 + k * dil;   // always even -> 8B aligned
#pragma unroll
    for (int i = 0; i < 8; i++) {
        int idx = tid + i * 256;
        int f4 = idx & 63, ci = idx >> 6;
        const float* src = hp + (size_t)(ci0 + ci) * TS + toff + f4 * 4;
        pB[i][0] = *(const float2*)src;
        pB[i][1] = *(const float2*)(src + 2);
    }
}

__global__ __launch_bounds__(256) void dilconv_kernel(
    const float* __restrict__ hin, const float* __restrict__ w,
    const float* __restrict__ bias, float* __restrict__ hout,
    int dil, int len_out)
{
    extern __shared__ float sm[];
    const int tid = threadIdx.x;
    const int tx = tid & 31, ty = tid >> 5;
    const int t0 = blockIdx.x * 256;
    const int c0 = blockIdx.y * 64;
    const int p  = blockIdx.z;
    const float* __restrict__ hp = hin + (size_t)p * (HIDC * TS);

    ull_t acc[8][4];
#pragma unroll
    for (int i = 0; i < 8; i++)
#pragma unroll
        for (int j = 0; j < 4; j++) acc[i][j] = 0ull;

    float pA[8];
    float2 pB[8][2];
    dc_loadA(w, c0, tid, 0, pA);
    dc_loadB(hp, t0, dil, tid, 0, pB);

#pragma unroll 1
    for (int ch = 0; ch < 24; ch++) {
        float* Asw = sm + (ch & 1) * STAGE_FLOATS;
        float* Bsw = Asw + AS_FLOATS;
        // store staged regs (chunk ch). Safe: every warp passed the sync of
        // iter ch-1, which is after its compute(ch-2) — the last reader of
        // this stage.
#pragma unroll
        for (int i = 0; i < 8; i++) {
            int idx = tid + i * 256;
            Asw[(idx & 31) * 68 + (idx >> 5)] = pA[i];
        }
#pragma unroll
        for (int i = 0; i < 8; i++) {
            int idx = tid + i * 256;
            int f4 = idx & 63, ci = idx >> 6;
            *(float4*)&Bsw[ci * 256 + f4 * 4] =
                make_float4(pB[i][0].x, pB[i][0].y, pB[i][1].x, pB[i][1].y);
        }
        __syncthreads();
        if (ch + 1 < 24) {
            dc_loadA(w, c0, tid, ch + 1, pA);
            dc_loadB(hp, t0, dil, tid, ch + 1, pB);
        }
        compute32(Asw, Bsw, tx, ty, acc);
    }

    float* __restrict__ op = hout + (size_t)p * (HIDC * TS);
#pragma unroll
    for (int ii = 0; ii < 8; ii++) {
        int c = c0 + ((ii < 4) ? (ty * 4 + ii) : (32 + ty * 4 + ii - 4));
        float bvv = bias[c];
        const float* rp = hp + (size_t)c * TS + dil;
        float* o = op + (size_t)c * TS;
#pragma unroll
        for (int g = 0; g < 2; g++) {
            int t = t0 + g * 128 + tx * 4;
            float2 u0 = unpack2(acc[ii][g * 2 + 0]);
            float2 u1 = unpack2(acc[ii][g * 2 + 1]);
            float v[4] = {u0.x, u0.y, u1.x, u1.y};
#pragma unroll
            for (int e = 0; e < 4; e++) {
                if (t + e < len_out)
                    o[t + e] = fmaxf(v[e] + bvv, 0.f) + rp[t + e];
            }
        }
    }
}

// ---------------------------------------------------------------------------
// Profile head: out[p][t] = softplus(sum_{c,j} h[p][c][t+j] * wp[c][j] + bp)
// ---------------------------------------------------------------------------
__global__ __launch_bounds__(256) void profile_kernel(
    const float* __restrict__ h, const float* __restrict__ wp,
    const float* __restrict__ bp, float* __restrict__ out)
{
    __shared__ float ws[64 * 75];
    __shared__ float red[256];
    const int tid = threadIdx.x;
    const int tt = tid & 63, g = tid >> 6;
    const int p = blockIdx.y;
    const int t = blockIdx.x * 64 + tt;
    const float* __restrict__ hp = h + (size_t)p * (HIDC * TS);

    float acc = 0.f;
#pragma unroll 1
    for (int cb = 0; cb < HIDC; cb += 64) {
        __syncthreads();
        for (int idx = tid; idx < 64 * 75; idx += 256) ws[idx] = wp[cb * 75 + idx];
        __syncthreads();
#pragma unroll 1
        for (int cc = 0; cc < 16; cc++) {
            int c = cb + g * 16 + cc;
            const float* hr = hp + (size_t)c * TS + t;
            const float* wr = ws + (g * 16 + cc) * 75;
            float s = 0.f;
#pragma unroll
            for (int j = 0; j < 75; j++) s = fmaf(hr[j], wr[j], s);
            acc += s;
        }
    }
    red[tid] = acc;
    __syncthreads();
    if (g == 0 && t < 418) {
        float tot = red[tt] + red[tt + 64] + red[tt + 128] + red[tt + 192] + bp[0];
        out[128 + p * 418 + t] = softplusf(tot);
    }
}

// ---------------------------------------------------------------------------
// ATPM head
// ---------------------------------------------------------------------------
__global__ __launch_bounds__(256) void atpm_kernel(
    const float* __restrict__ h, const float* __restrict__ wa,
    const float* __restrict__ ba, float* __restrict__ out)
{
    __shared__ float red[256];
    const int tid = threadIdx.x;
    const int p = blockIdx.x;
    const float* __restrict__ hr = h + (size_t)p * (HIDC * TS) + (size_t)tid * TS;
    float s = 0.f;
#pragma unroll 1
    for (int t4 = 0; t4 < 492; t4 += 4) {
        float4 v = *(const float4*)(hr + t4);
        s += (v.x + v.y) + (v.z + v.w);
    }
    red[tid] = (s * (1.0f / 492.0f)) * wa[tid];
    __syncthreads();
    for (int off = 128; off > 0; off >>= 1) {
        if (tid < off) red[tid] += red[tid + off];
        __syncthreads();
    }
    if (tid == 0) out[p] = softplusf(red[0] + ba[0]);
}

// ---------------------------------------------------------------------------
extern "C" void kernel_launch(void* const* d_in, const int* in_sizes, int n_in,
                              void* d_out, int out_size)
{
    (void)out_size;
    int pbase = 4;
    if (n_in == 11) pbase = 3;
    else if (n_in == 12 && in_sizes[3] != 1) pbase = 3;

    const float* x      = (const float*)d_in[0];
    const float* w_proj = (const float*)d_in[pbase + 0];
    const float* b_proj = (const float*)d_in[pbase + 1];
    const float* w_dil  = (const float*)d_in[pbase + 2];
    const float* b_dil  = (const float*)d_in[pbase + 3];
    const float* w_prof = (const float*)d_in[pbase + 4];
    const float* b_prof = (const float*)d_in[pbase + 5];
    const float* w_atpm = (const float*)d_in[pbase + 6];
    const float* b_atpm = (const float*)d_in[pbase + 7];
    float* out = (float*)d_out;

    float *bufA, *bufB;
    cudaGetSymbolAddress((void**)&bufA, g_bufA);
    cudaGetSymbolAddress((void**)&bufB, g_bufB);

    // allow 83KB dynamic smem (persistent attribute; capture-safe, idempotent)
    cudaFuncSetAttribute(proj_kernel,
                         cudaFuncAttributeMaxDynamicSharedMemorySize, SMEM_BYTES);
    cudaFuncSetAttribute(dilconv_kernel,
                         cudaFuncAttributeMaxDynamicSharedMemorySize, SMEM_BYTES);

    // 1x1 projection GEMM: 128000 pos x 256 ch, K=640
    proj_kernel<<<dim3(500, 4), 256, SMEM_BYTES>>>(x, w_proj, b_proj, bufA);

    // dilated conv tower, ping-pong buffers
    static const int lens[8] = {1000, 996, 988, 972, 940, 876, 748, 492};
    float* cur = bufA;
    float* nxt = bufB;
    for (int l = 0; l < 7; l++) {
        int dil = 2 << l;
        int lo = lens[l + 1];
        dim3 grid((lo + 255) / 256, 4, NPEAK);
        dilconv_kernel<<<grid, 256, SMEM_BYTES>>>(cur, w_dil + (size_t)l * 196608,
                                                  b_dil + l * 256, nxt, dil, lo);
        float* tmp = cur; cur = nxt; nxt = tmp;
    }

    // heads (final activations live in `cur`, len 492)
    atpm_kernel<<<NPEAK, 256>>>(cur, w_atpm, b_atpm, out);
    profile_kernel<<<dim3(7, NPEAK), 256>>>(cur, w_prof, b_prof, out);
}

// round 6
// speedup vs baseline: 1.1962x; 1.1962x over previous
#include <cuda_runtime.h>
#include <cstdint>
#include <cstddef>

// ---------------------------------------------------------------------------
// ConvPool (BPNet-style): 1x1 proj GEMM -> 7x dilated conv tower (residual,
// relu) -> profile conv (K=75) + atpm head (mean -> linear -> softplus).
// R6: dilconv uses cp.async double-buffered B tiles + __launch_bounds__(256,2)
// for 2 CTAs/SM (16 warps). proj reverted to the proven R4 structure.
// ---------------------------------------------------------------------------

#define NPEAK 128          // B * NUM_PEAKS
#define HIDC  256
#define MOTIF_C 640
#define TS    1000         // per-row t stride
#define BUF_ELEMS (NPEAK * HIDC * TS + 4096)

#define AS_FLOATS (32 * 68)
#define STAGE_FLOATS (AS_FLOATS + 32 * 256)   // 10368 floats = 41472 B
#define DC_SMEM_BYTES (2 * STAGE_FLOATS * 4)  // 82944 B (2 stages)

typedef unsigned long long ull_t;

__device__ float g_bufA[BUF_ELEMS];
__device__ float g_bufB[BUF_ELEMS];

__device__ __forceinline__ float softplusf(float x) {
    return fmaxf(x, 0.0f) + log1pf(expf(-fabsf(x)));
}

__device__ __forceinline__ ull_t pack2(float x, float y) {
    ull_t r;
    asm("mov.b64 %0, {%1, %2};" : "=l"(r) : "f"(x), "f"(y));
    return r;
}
__device__ __forceinline__ float2 unpack2(ull_t v) {
    float2 r;
    asm("mov.b64 {%0, %1}, %2;" : "=f"(r.x), "=f"(r.y) : "l"(v));
    return r;
}
__device__ __forceinline__ void ffma2(ull_t& d, ull_t a, ull_t b) {
    asm("fma.rn.f32x2 %0, %1, %2, %0;" : "+l"(d) : "l"(a), "l"(b));
}

// 8x8 micro-kernel (8 ch x 4 f32x2 pairs) over a 32-deep K tile.
// As: [k][c] stride 68 (warp-uniform broadcast reads); Bs: [k][t] stride 256.
__device__ __forceinline__ void compute32(
    const float* __restrict__ As, const float* __restrict__ Bs,
    int tx, int ty, ull_t acc[8][4])
{
#pragma unroll
    for (int kk = 0; kk < 32; kk++) {
        float4 a0 = *(const float4*)(As + kk * 68 + ty * 4);
        float4 a1 = *(const float4*)(As + kk * 68 + 32 + ty * 4);
        ull_t av[8];
        av[0] = pack2(a0.x, a0.x); av[1] = pack2(a0.y, a0.y);
        av[2] = pack2(a0.z, a0.z); av[3] = pack2(a0.w, a0.w);
        av[4] = pack2(a1.x, a1.x); av[5] = pack2(a1.y, a1.y);
        av[6] = pack2(a1.z, a1.z); av[7] = pack2(a1.w, a1.w);
        ulonglong2 b0 = *(const ulonglong2*)(Bs + kk * 256 + tx * 4);
        ulonglong2 b1 = *(const ulonglong2*)(Bs + kk * 256 + 128 + tx * 4);
        ull_t bv[4] = {b0.x, b0.y, b1.x, b1.y};
#pragma unroll
        for (int i = 0; i < 8; i++)
#pragma unroll
            for (int j = 0; j < 4; j++)
                ffma2(acc[i][j], av[i], bv[j]);
    }
}

// ---------------------------------------------------------------------------
// Projection GEMM (R4 structure: static smem, register-staged prefetch)
// ---------------------------------------------------------------------------
__device__ __forceinline__ void pj_loadA(const float* __restrict__ w, int c0,
                                         int tid, int k0, float pA[8])
{
#pragma unroll
    for (int i = 0; i < 8; i++) {
        int idx = tid + i * 256;
        int kk = idx & 31, cc = idx >> 5;
        pA[i] = w[(size_t)(c0 + cc) * MOTIF_C + k0 + kk];
    }
}
__device__ __forceinline__ void pj_loadB(const float* __restrict__ x, int pos0,
                                         int tid, int k0, float4 pB[8])
{
#pragma unroll
    for (int i = 0; i < 8; i++) {
        int idx = tid + i * 256;
        int f4 = idx & 7, pl = idx >> 3;
        pB[i] = *(const float4*)(x + (size_t)(pos0 + pl) * MOTIF_C + k0 + f4 * 4);
    }
}

__global__ __launch_bounds__(256) void proj_kernel(
    const float* __restrict__ x, const float* __restrict__ w,
    const float* __restrict__ bias, float* __restrict__ out)
{
    __shared__ float As[32][68];
    __shared__ float Bs[32][256];
    const int tid = threadIdx.x;
    const int tx = tid & 31, ty = tid >> 5;
    const int pos0 = blockIdx.x * 256;
    const int c0 = blockIdx.y * 64;

    ull_t acc[8][4];
#pragma unroll
    for (int i = 0; i < 8; i++)
#pragma unroll
        for (int j = 0; j < 4; j++) acc[i][j] = 0ull;

    float pA[8];
    float4 pB[8];
    pj_loadA(w, c0, tid, 0, pA);
    pj_loadB(x, pos0, tid, 0, pB);

#pragma unroll 1
    for (int k0 = 0; k0 < MOTIF_C; k0 += 32) {
        __syncthreads();
#pragma unroll
        for (int i = 0; i < 8; i++) {
            int idx = tid + i * 256;
            As[idx & 31][idx >> 5] = pA[i];
        }
#pragma unroll
        for (int i = 0; i < 8; i++) {
            int idx = tid + i * 256;
            int f4 = idx & 7, pl = idx >> 3;
            Bs[f4 * 4 + 0][pl] = pB[i].x;
            Bs[f4 * 4 + 1][pl] = pB[i].y;
            Bs[f4 * 4 + 2][pl] = pB[i].z;
            Bs[f4 * 4 + 3][pl] = pB[i].w;
        }
        __syncthreads();
        if (k0 + 32 < MOTIF_C) {
            pj_loadA(w, c0, tid, k0 + 32, pA);
            pj_loadB(x, pos0, tid, k0 + 32, pB);
        }
        compute32(&As[0][0], &Bs[0][0], tx, ty, acc);
    }

#pragma unroll
    for (int ii = 0; ii < 8; ii++) {
        int c = c0 + ((ii < 4) ? (ty * 4 + ii) : (32 + ty * 4 + ii - 4));
        float bvv = bias[c];
#pragma unroll
        for (int g = 0; g < 2; g++) {
            float2 u0 = unpack2(acc[ii][g * 2 + 0]);
            float2 u1 = unpack2(acc[ii][g * 2 + 1]);
            float v[4] = {u0.x, u0.y, u1.x, u1.y};
#pragma unroll
            for (int e = 0; e < 4; e++) {
                int pos = pos0 + g * 128 + tx * 4 + e;
                int pb = pos / 1000;
                int tb = pos - pb * 1000;
                out[(size_t)pb * (HIDC * TS) + (size_t)c * TS + tb] = v[e] + bvv;
            }
        }
    }
}

// ---------------------------------------------------------------------------
// Dilated conv: cp.async B pipeline, 2-stage, 2 CTAs/SM.
// ---------------------------------------------------------------------------
__device__ __forceinline__ void dc_loadA(const float* __restrict__ w, int c0,
                                         int tid, int chunk, float pA[8])
{
    int k = chunk >> 3, ci0 = (chunk & 7) << 5;
#pragma unroll
    for (int i = 0; i < 8; i++) {
        int idx = tid + i * 256;
        int ci = idx & 31, cc = idx >> 5;
        pA[i] = w[(size_t)(c0 + cc) * 768 + (ci0 + ci) * 3 + k];
    }
}

// issue 16KB of B tile via cp.async (2 x 8B per thread per i; toff even so
// 8B-aligned), then commit the group.
__device__ __forceinline__ void dc_issueB(const float* __restrict__ hp, int t0,
                                          int dil, int tid, int chunk,
                                          float* Bsw)
{
    int k = chunk >> 3, ci0 = (chunk & 7) << 5;
    int toff = t0 + k * dil;
    unsigned bbase = (unsigned)__cvta_generic_to_shared(Bsw);
#pragma unroll
    for (int i = 0; i < 8; i++) {
        int idx = tid + i * 256;
        int f4 = idx & 63, ci = idx >> 6;
        const float* src = hp + (size_t)(ci0 + ci) * TS + toff + f4 * 4;
        unsigned dst = bbase + (unsigned)(ci * 256 + f4 * 4) * 4u;
        asm volatile("cp.async.ca.shared.global [%0], [%1], 8;"
                     :: "r"(dst), "l"(src) : "memory");
        asm volatile("cp.async.ca.shared.global [%0], [%1], 8;"
                     :: "r"(dst + 8), "l"(src + 2) : "memory");
    }
    asm volatile("cp.async.commit_group;" ::: "memory");
}

__global__ __launch_bounds__(256, 2) void dilconv_kernel(
    const float* __restrict__ hin, const float* __restrict__ w,
    const float* __restrict__ bias, float* __restrict__ hout,
    int dil, int len_out)
{
    extern __shared__ float sm[];
    const int tid = threadIdx.x;
    const int tx = tid & 31, ty = tid >> 5;
    const int t0 = blockIdx.x * 256;
    const int c0 = blockIdx.y * 64;
    const int p  = blockIdx.z;
    const float* __restrict__ hp = hin + (size_t)p * (HIDC * TS);

    ull_t acc[8][4];
#pragma unroll
    for (int i = 0; i < 8; i++)
#pragma unroll
        for (int j = 0; j < 4; j++) acc[i][j] = 0ull;

    float pA[8];
    dc_loadA(w, c0, tid, 0, pA);
    dc_issueB(hp, t0, dil, tid, 0, sm + AS_FLOATS);   // B(0) -> stage 0

#pragma unroll 1
    for (int ch = 0; ch < 24; ch++) {
        float* Asw = sm + (ch & 1) * STAGE_FLOATS;
        float* Bsw = Asw + AS_FLOATS;
        // store A(ch). Safe: all warps passed sync(ch-1), i.e. finished
        // compute(ch-2), the last reader of this stage's A.
#pragma unroll
        for (int i = 0; i < 8; i++) {
            int idx = tid + i * 256;
            Asw[(idx & 31) * 68 + (idx >> 5)] = pA[i];
        }
        asm volatile("cp.async.wait_group 0;" ::: "memory");  // B(ch) landed
        __syncthreads();
        if (ch + 1 < 24) {
            // B(ch+1) -> stage (ch+1)&1: all warps finished compute(ch-1),
            // the last reader of that stage, because they passed sync(ch).
            dc_issueB(hp, t0, dil, tid, ch + 1,
                      sm + ((ch + 1) & 1) * STAGE_FLOATS + AS_FLOATS);
            dc_loadA(w, c0, tid, ch + 1, pA);
        }
        compute32(Asw, Bsw, tx, ty, acc);
    }

    float* __restrict__ op = hout + (size_t)p * (HIDC * TS);
#pragma unroll
    for (int ii = 0; ii < 8; ii++) {
        int c = c0 + ((ii < 4) ? (ty * 4 + ii) : (32 + ty * 4 + ii - 4));
        float bvv = bias[c];
        const float* rp = hp + (size_t)c * TS + dil;
        float* o = op + (size_t)c * TS;
#pragma unroll
        for (int g = 0; g < 2; g++) {
            int t = t0 + g * 128 + tx * 4;
            float2 u0 = unpack2(acc[ii][g * 2 + 0]);
            float2 u1 = unpack2(acc[ii][g * 2 + 1]);
            float v[4] = {u0.x, u0.y, u1.x, u1.y};
#pragma unroll
            for (int e = 0; e < 4; e++) {
                if (t + e < len_out)
                    o[t + e] = fmaxf(v[e] + bvv, 0.f) + rp[t + e];
            }
        }
    }
}

// ---------------------------------------------------------------------------
// Profile head: out[p][t] = softplus(sum_{c,j} h[p][c][t+j] * wp[c][j] + bp)
// ---------------------------------------------------------------------------
__global__ __launch_bounds__(256) void profile_kernel(
    const float* __restrict__ h, const float* __restrict__ wp,
    const float* __restrict__ bp, float* __restrict__ out)
{
    __shared__ float ws[64 * 75];
    __shared__ float red[256];
    const int tid = threadIdx.x;
    const int tt = tid & 63, g = tid >> 6;
    const int p = blockIdx.y;
    const int t = blockIdx.x * 64 + tt;
    const float* __restrict__ hp = h + (size_t)p * (HIDC * TS);

    float acc = 0.f;
#pragma unroll 1
    for (int cb = 0; cb < HIDC; cb += 64) {
        __syncthreads();
        for (int idx = tid; idx < 64 * 75; idx += 256) ws[idx] = wp[cb * 75 + idx];
        __syncthreads();
#pragma unroll 1
        for (int cc = 0; cc < 16; cc++) {
            int c = cb + g * 16 + cc;
            const float* hr = hp + (size_t)c * TS + t;
            const float* wr = ws + (g * 16 + cc) * 75;
            float s = 0.f;
#pragma unroll
            for (int j = 0; j < 75; j++) s = fmaf(hr[j], wr[j], s);
            acc += s;
        }
    }
    red[tid] = acc;
    __syncthreads();
    if (g == 0 && t < 418) {
        float tot = red[tt] + red[tt + 64] + red[tt + 128] + red[tt + 192] + bp[0];
        out[128 + p * 418 + t] = softplusf(tot);
    }
}

// ---------------------------------------------------------------------------
// ATPM head
// ---------------------------------------------------------------------------
__global__ __launch_bounds__(256) void atpm_kernel(
    const float* __restrict__ h, const float* __restrict__ wa,
    const float* __restrict__ ba, float* __restrict__ out)
{
    __shared__ float red[256];
    const int tid = threadIdx.x;
    const int p = blockIdx.x;
    const float* __restrict__ hr = h + (size_t)p * (HIDC * TS) + (size_t)tid * TS;
    float s = 0.f;
#pragma unroll 1
    for (int t4 = 0; t4 < 492; t4 += 4) {
        float4 v = *(const float4*)(hr + t4);
        s += (v.x + v.y) + (v.z + v.w);
    }
    red[tid] = (s * (1.0f / 492.0f)) * wa[tid];
    __syncthreads();
    for (int off = 128; off > 0; off >>= 1) {
        if (tid < off) red[tid] += red[tid + off];
        __syncthreads();
    }
    if (tid == 0) out[p] = softplusf(red[0] + ba[0]);
}

// ---------------------------------------------------------------------------
extern "C" void kernel_launch(void* const* d_in, const int* in_sizes, int n_in,
                              void* d_out, int out_size)
{
    (void)out_size;
    int pbase = 4;
    if (n_in == 11) pbase = 3;
    else if (n_in == 12 && in_sizes[3] != 1) pbase = 3;

    const float* x      = (const float*)d_in[0];
    const float* w_proj = (const float*)d_in[pbase + 0];
    const float* b_proj = (const float*)d_in[pbase + 1];
    const float* w_dil  = (const float*)d_in[pbase + 2];
    const float* b_dil  = (const float*)d_in[pbase + 3];
    const float* w_prof = (const float*)d_in[pbase + 4];
    const float* b_prof = (const float*)d_in[pbase + 5];
    const float* w_atpm = (const float*)d_in[pbase + 6];
    const float* b_atpm = (const float*)d_in[pbase + 7];
    float* out = (float*)d_out;

    float *bufA, *bufB;
    cudaGetSymbolAddress((void**)&bufA, g_bufA);
    cudaGetSymbolAddress((void**)&bufB, g_bufB);

    cudaFuncSetAttribute(dilconv_kernel,
                         cudaFuncAttributeMaxDynamicSharedMemorySize,
                         DC_SMEM_BYTES);

    // 1x1 projection GEMM: 128000 pos x 256 ch, K=640
    proj_kernel<<<dim3(500, 4), 256>>>(x, w_proj, b_proj, bufA);

    // dilated conv tower, ping-pong buffers
    static const int lens[8] = {1000, 996, 988, 972, 940, 876, 748, 492};
    float* cur = bufA;
    float* nxt = bufB;
    for (int l = 0; l < 7; l++) {
        int dil = 2 << l;
        int lo = lens[l + 1];
        dim3 grid((lo + 255) / 256, 4, NPEAK);
        dilconv_kernel<<<grid, 256, DC_SMEM_BYTES>>>(
            cur, w_dil + (size_t)l * 196608, b_dil + l * 256, nxt, dil, lo);
        float* tmp = cur; cur = nxt; nxt = tmp;
    }

    // heads (final activations live in `cur`, len 492)
    atpm_kernel<<<NPEAK, 256>>>(cur, w_atpm, b_atpm, out);
    profile_kernel<<<dim3(7, NPEAK), 256>>>(cur, w_prof, b_prof, out);
}